// round 11
// baseline (speedup 1.0000x reference)
#include <cuda_runtime.h>
#include <cuda_fp16.h>
#include <cstdint>
#include <cstddef>

#define BATCH 32768
#define IN_F  512
#define OUT_F 512
#define KP    4096             // K' = IN_F * 8  (d = 1..8; d=0 folded into bias)

#define BM 128
#define BN 256
#define BK 64
#define NITER (KP / BK)        // 64
#define NSLOT 5                // A ring slots
#define COEF_SCALE 4096.0f
#define OUT_SCALE  (1.0f / 4096.0f)

// ---------------- smem layout (bytes) ----------------------------------------
// A ring:  5 x 16384           [0, 81920)
// B stages: 2 x 32768          [81920, 147456)
// Tc state: 128 x 272          [147456, 182272)
// Tp state: 128 x 272          [182272, 217088)
#define OFF_A(s) ((s) * 16384u)
#define OFF_B(s) (81920u + (s) * 32768u)
#define OFF_SC   147456u
#define OFF_SP   182272u
#define SMEM_TOTAL 217088

// ---------------- scratch ----------------------------------------------------
__device__ __align__(1024) __half g_B[(size_t)OUT_F * KP];   // 4 MB
__device__ float g_bias[OUT_F];

// ---------------- helpers ----------------------------------------------------
__device__ __forceinline__ uint32_t smem_u32(const void* p) {
    uint32_t a;
    asm("{ .reg .u64 t; cvta.to.shared.u64 t, %1; cvt.u32.u64 %0, t; }" : "=r"(a) : "l"(p));
    return a;
}
__device__ __forceinline__ uint32_t pack_h2(float lo, float hi) {
    uint32_t r;
    asm("cvt.rn.f16x2.f32 %0, %1, %2;" : "=r"(r) : "f"(hi), "f"(lo));
    return r;
}
__device__ __forceinline__ void cp_async16(uint32_t dst, const void* src) {
    asm volatile("cp.async.cg.shared.global [%0], [%1], 16;" :: "r"(dst), "l"(src) : "memory");
}
#define CP_COMMIT() asm volatile("cp.async.commit_group;" ::: "memory")
#define CP_WAIT(n)  asm volatile("cp.async.wait_group %0;" :: "n"(n) : "memory")

__device__ __forceinline__ void ldsm_x4(uint32_t f[4], uint32_t addr) {
    asm volatile("ldmatrix.sync.aligned.m8n8.x4.shared.b16 {%0,%1,%2,%3}, [%4];"
                 : "=r"(f[0]), "=r"(f[1]), "=r"(f[2]), "=r"(f[3]) : "r"(addr));
}
__device__ __forceinline__ void mma16816(float c[4], const uint32_t a[4],
                                         uint32_t b0, uint32_t b1) {
    asm volatile(
        "mma.sync.aligned.m16n8k16.row.col.f32.f16.f16.f32 "
        "{%0,%1,%2,%3}, {%4,%5,%6,%7}, {%8,%9}, {%0,%1,%2,%3};"
        : "+f"(c[0]), "+f"(c[1]), "+f"(c[2]), "+f"(c[3])
        : "r"(a[0]), "r"(a[1]), "r"(a[2]), "r"(a[3]), "r"(b0), "r"(b1));
}

// write one 8-element fp16 group of an A tile (row m, group j)
__device__ __forceinline__ void sts_A(char* sm, uint32_t slot_off, int m, int j,
                                      float4 lo, float4 hi) {
    uint4 h;
    h.x = pack_h2(lo.x, lo.y); h.y = pack_h2(lo.z, lo.w);
    h.z = pack_h2(hi.x, hi.y); h.w = pack_h2(hi.z, hi.w);
    *reinterpret_cast<uint4*>(sm + slot_off + m * 128 + ((j << 4) ^ ((m & 7) << 4))) = h;
}

// ---------------- gen_b: B'[o, iblk*512+(d-1)*64+ii] = 4096*C[i,o,d]; bias ---
__global__ void gen_b_kernel(const float* __restrict__ c, __half* __restrict__ B,
                             float* __restrict__ bias) {
    __shared__ float red[IN_F];
    int o = blockIdx.x;
    int i = threadIdx.x;                  // 0..511
    const float* src = c + ((size_t)i * OUT_F + o) * 9;
    red[i] = src[0];
    __half* dst = B + (size_t)o * KP + (i >> 6) * 512 + (i & 63);
#pragma unroll
    for (int d = 1; d <= 8; d++)
        dst[(d - 1) * 64] = __float2half_rn(src[d] * COEF_SCALE);
    __syncthreads();
#pragma unroll
    for (int s = IN_F / 2; s > 0; s >>= 1) {
        if (i < s) red[i] += red[i + s];
        __syncthreads();
    }
    if (i == 0) bias[o] = red[0] * COEF_SCALE;
}

// ---------------- fused warp-specialized GEMM: M=32768 N=512 K'=4096 ---------
// warps 0..7 : pure ldmatrix+mma mainloop
// warps 8..11: burst A generation (register-resident recurrence) + B cp.async
__global__ __launch_bounds__(384, 1)
void gemm_kernel(const float* __restrict__ x, const __half* __restrict__ Bw,
                 const float* __restrict__ bias, float* __restrict__ out) {
    extern __shared__ __align__(1024) char smem[];
    uint32_t sb = smem_u32(smem);
    int tid = threadIdx.x;
    int wid = tid >> 5, lid = tid & 31;
    int m0 = blockIdx.y * BM;
    int n0 = blockIdx.x * BN;
    bool is_gen = (wid >= 8);
    int gtid = tid - 256;          // 0..127 for gen warps (row m)
    int wm = wid & 3, wn = wid >> 2;

    float acc[2][16][4];
    float4 u[16];                  // gen: tanh(x) for current i-block, 8 per pair

    int g_c = gtid & 7;

#define ISSUE_B_G(it_)                                                            \
    do {                                                                          \
        uint32_t bb_ = sb + OFF_B((it_) & 1);                                     \
        const char* bgm_ = (const char*)(Bw + (size_t)n0 * KP + (it_) * BK);      \
        _Pragma("unroll")                                                         \
        for (int r_ = 0; r_ < 16; r_++) {                                         \
            int row_ = (gtid >> 3) + r_ * 16;                                     \
            uint32_t dst_ = bb_ + row_ * 128 + ((g_c ^ (row_ & 7)) << 4);         \
            cp_async16(dst_, bgm_ + (size_t)row_ * (KP * 2) + g_c * 16);          \
        }                                                                         \
    } while (0)

    if (is_gen) {
        ISSUE_B_G(0); CP_COMMIT();
        ISSUE_B_G(1); CP_COMMIT();
        // prologue: chunk 0 (d=1, block 0): u = tanh(x), A = u
        const float* xp = x + (size_t)(m0 + gtid) * IN_F;
#pragma unroll
        for (int j = 0; j < 8; j++) {
            float4 xa = *reinterpret_cast<const float4*>(xp + j * 8);
            float4 xb = *reinterpret_cast<const float4*>(xp + j * 8 + 4);
            float4 ua, ub;
            ua.x = tanhf(xa.x); ua.y = tanhf(xa.y); ua.z = tanhf(xa.z); ua.w = tanhf(xa.w);
            ub.x = tanhf(xb.x); ub.y = tanhf(xb.y); ub.z = tanhf(xb.z); ub.w = tanhf(xb.w);
            u[2 * j] = ua; u[2 * j + 1] = ub;
            sts_A(smem, OFF_A(0), gtid, j, ua, ub);
        }
        CP_WAIT(1);                 // B0 landed
    } else {
        int ncol = (lid & 3) * 2;
#pragma unroll
        for (int ni = 0; ni < 16; ni++) {
            int n = n0 + wn * 128 + ni * 8 + ncol;
            float b0 = __ldg(bias + n);
            float b1 = __ldg(bias + n + 1);
#pragma unroll
            for (int mi = 0; mi < 2; mi++) {
                acc[mi][ni][0] = b0; acc[mi][ni][1] = b1;
                acc[mi][ni][2] = b0; acc[mi][ni][3] = b1;
            }
        }
    }
    __syncthreads();

    int lr = lid & 7;
    int lt = lid >> 3;
    int asl = 0;                   // MMA A-slot (c mod 5)

    for (int c = 0; c < NITER; c++) {
        if (is_gen) {
            if ((c & 3) == 0) {
                // burst: produce chunks c+1 .. min(c+4,63)
                int m = gtid;
                char* scrow = smem + OFF_SC + m * 272;
                char* sprow = smem + OFF_SP + m * 272;
                uint32_t s1 = OFF_A((c + 1) % NSLOT);
                uint32_t s2 = OFF_A((c + 2) % NSLOT);
                uint32_t s3 = OFF_A((c + 3) % NSLOT);
                uint32_t s4 = OFF_A((c + 4) % NSLOT);
                if ((c & 7) == 0) {
                    // early burst: d = 2,3,4,5; entry (Tc,Tp) = (u,1); store (T5,T4)
#pragma unroll
                    for (int j = 0; j < 8; j++) {
                        float4 ua = u[2 * j], ub = u[2 * j + 1];
                        float4 ca = ua, cb = ub;                  // T1
                        float4 pa = make_float4(1.f, 1.f, 1.f, 1.f), pb = pa; // T0
                        float4 na, nb;
#pragma unroll
                        for (int s = 0; s < 4; s++) {
                            na.x = __fmaf_rn(2.f * ua.x, ca.x, -pa.x);
                            na.y = __fmaf_rn(2.f * ua.y, ca.y, -pa.y);
                            na.z = __fmaf_rn(2.f * ua.z, ca.z, -pa.z);
                            na.w = __fmaf_rn(2.f * ua.w, ca.w, -pa.w);
                            nb.x = __fmaf_rn(2.f * ub.x, cb.x, -pb.x);
                            nb.y = __fmaf_rn(2.f * ub.y, cb.y, -pb.y);
                            nb.z = __fmaf_rn(2.f * ub.z, cb.z, -pb.z);
                            nb.w = __fmaf_rn(2.f * ub.w, cb.w, -pb.w);
                            uint32_t so = (s == 0) ? s1 : (s == 1) ? s2 : (s == 2) ? s3 : s4;
                            sts_A(smem, so, m, j, na, nb);
                            pa = ca; pb = cb; ca = na; cb = nb;
                        }
                        // store state (Tc=T5, Tp=T4)
                        *reinterpret_cast<float4*>(scrow + j * 32)      = ca;
                        *reinterpret_cast<float4*>(scrow + j * 32 + 16) = cb;
                        *reinterpret_cast<float4*>(sprow + j * 32)      = pa;
                        *reinterpret_cast<float4*>(sprow + j * 32 + 16) = pb;
                    }
                } else {
                    // late burst: d = 6,7,8 (+ d=1 of next block if it exists)
                    bool hasd1 = (c + 4 < NITER);
                    const float* xp = x + (size_t)(m0 + m) * IN_F + ((c + 4) >> 3) * 64;
#pragma unroll
                    for (int j = 0; j < 8; j++) {
                        float4 ua = u[2 * j], ub = u[2 * j + 1];
                        float4 ca = *reinterpret_cast<const float4*>(scrow + j * 32);
                        float4 cb = *reinterpret_cast<const float4*>(scrow + j * 32 + 16);
                        float4 pa = *reinterpret_cast<const float4*>(sprow + j * 32);
                        float4 pb = *reinterpret_cast<const float4*>(sprow + j * 32 + 16);
                        float4 na, nb;
#pragma unroll
                        for (int s = 0; s < 3; s++) {
                            na.x = __fmaf_rn(2.f * ua.x, ca.x, -pa.x);
                            na.y = __fmaf_rn(2.f * ua.y, ca.y, -pa.y);
                            na.z = __fmaf_rn(2.f * ua.z, ca.z, -pa.z);
                            na.w = __fmaf_rn(2.f * ua.w, ca.w, -pa.w);
                            nb.x = __fmaf_rn(2.f * ub.x, cb.x, -pb.x);
                            nb.y = __fmaf_rn(2.f * ub.y, cb.y, -pb.y);
                            nb.z = __fmaf_rn(2.f * ub.z, cb.z, -pb.z);
                            nb.w = __fmaf_rn(2.f * ub.w, cb.w, -pb.w);
                            uint32_t so = (s == 0) ? s1 : (s == 1) ? s2 : s3;
                            sts_A(smem, so, m, j, na, nb);
                            pa = ca; pb = cb; ca = na; cb = nb;
                        }
                        if (hasd1) {
                            float4 xa = *reinterpret_cast<const float4*>(xp + j * 8);
                            float4 xb = *reinterpret_cast<const float4*>(xp + j * 8 + 4);
                            float4 va, vb;
                            va.x = tanhf(xa.x); va.y = tanhf(xa.y);
                            va.z = tanhf(xa.z); va.w = tanhf(xa.w);
                            vb.x = tanhf(xb.x); vb.y = tanhf(xb.y);
                            vb.z = tanhf(xb.z); vb.w = tanhf(xb.w);
                            u[2 * j] = va; u[2 * j + 1] = vb;
                            sts_A(smem, s4, m, j, va, vb);
                        }
                    }
                }
            }
            CP_WAIT(0);             // B[c+1] landed
        } else {
            uint32_t abase = sb + OFF_A(asl);
            uint32_t bbase = sb + OFF_B(c & 1);
#pragma unroll
            for (int ks = 0; ks < 4; ks++) {
                uint32_t afr[2][4];
#pragma unroll
                for (int mi = 0; mi < 2; mi++) {
                    int m = wm * 32 + mi * 16 + (lt & 1) * 8 + lr;
                    int g = ks * 2 + (lt >> 1);
                    ldsm_x4(afr[mi], abase + m * 128 + ((g ^ (m & 7)) << 4));
                }
#pragma unroll
                for (int nb = 0; nb < 8; nb++) {
                    uint32_t bfr[4];
                    int n = wn * 128 + nb * 16 + (lt & 1) * 8 + lr;
                    int g = ks * 2 + (lt >> 1);
                    ldsm_x4(bfr, bbase + n * 128 + ((g ^ (n & 7)) << 4));
#pragma unroll
                    for (int h = 0; h < 2; h++)
#pragma unroll
                        for (int mi = 0; mi < 2; mi++)
                            mma16816(acc[mi][2 * nb + h], afr[mi], bfr[h], bfr[h + 2]);
                }
            }
        }
        asl = (asl == NSLOT - 1) ? 0 : asl + 1;
        __syncthreads();            // publishes A[c+1..], B[c+1]; certifies reads of A[c],B[c]
        if (is_gen && c + 2 < NITER) { ISSUE_B_G(c + 2); CP_COMMIT(); }
    }

    // ---------------- epilogue (MMA warps only) ----------------
    if (!is_gen) {
        int mrow = lid >> 2;
        int ncol = (lid & 3) * 2;
#pragma unroll
        for (int mi = 0; mi < 2; mi++) {
#pragma unroll
            for (int ni = 0; ni < 16; ni++) {
                int n = n0 + wn * 128 + ni * 8 + ncol;
                int m_lo = m0 + wm * 32 + mi * 16 + mrow;
                float2 v0, v1;
                v0.x = acc[mi][ni][0] * OUT_SCALE;
                v0.y = acc[mi][ni][1] * OUT_SCALE;
                v1.x = acc[mi][ni][2] * OUT_SCALE;
                v1.y = acc[mi][ni][3] * OUT_SCALE;
                *reinterpret_cast<float2*>(out + (size_t)m_lo * OUT_F + n) = v0;
                *reinterpret_cast<float2*>(out + (size_t)(m_lo + 8) * OUT_F + n) = v1;
            }
        }
    }
#undef ISSUE_B_G
}

// ---------------- launch ------------------------------------------------------
extern "C" void kernel_launch(void* const* d_in, const int* in_sizes, int n_in,
                              void* d_out, int out_size) {
    const float* x     = (const float*)d_in[0];
    const float* coeff = (const float*)d_in[1];
    float* out = (float*)d_out;

    void* pB = nullptr;
    void* pBias = nullptr;
    cudaGetSymbolAddress(&pB, g_B);
    cudaGetSymbolAddress(&pBias, g_bias);

    gen_b_kernel<<<OUT_F, IN_F>>>(coeff, (__half*)pB, (float*)pBias);

    cudaFuncSetAttribute(gemm_kernel, cudaFuncAttributeMaxDynamicSharedMemorySize,
                         SMEM_TOTAL);
    dim3 grid(OUT_F / BN, BATCH / BM);   // (2, 256)
    gemm_kernel<<<grid, 384, SMEM_TOTAL>>>(x, (const __half*)pB,
                                           (const float*)pBias, out);
}

// round 12
// speedup vs baseline: 1.4004x; 1.4004x over previous
#include <cuda_runtime.h>
#include <cuda_fp16.h>
#include <cstdint>
#include <cstddef>

#define BATCH 32768
#define IN_F  512
#define OUT_F 512
#define KP    4096             // K' = IN_F * 8  (d = 1..8; d=0 folded into bias)

#define BM 128
#define BN 256
#define BK 64
#define NSTAGE 4
#define NITER (KP / BK)        // 64
#define COEF_SCALE 4096.0f
#define OUT_SCALE  (1.0f / 4096.0f)

#define ASTAGE_BYTES (BM * 128)             // 16 KB
#define BSTAGE_BYTES (BN * 128)             // 32 KB
#define STAGE_BYTES  (ASTAGE_BYTES + BSTAGE_BYTES)
#define SMEM_TOTAL   (NSTAGE * STAGE_BYTES) // 192 KB

// ---------------- scratch ----------------------------------------------------
__device__ __align__(1024) __half g_A[(size_t)BATCH * KP];   // 256 MB
__device__ __align__(1024) __half g_B[(size_t)OUT_F * KP];   // 4 MB
__device__ float g_bias[OUT_F];

// ---------------- helpers ----------------------------------------------------
__device__ __forceinline__ uint32_t smem_u32(const void* p) {
    uint32_t a;
    asm("{ .reg .u64 t; cvta.to.shared.u64 t, %1; cvt.u32.u64 %0, t; }" : "=r"(a) : "l"(p));
    return a;
}
__device__ __forceinline__ void cp_async16(uint32_t dst, const void* src) {
    asm volatile("cp.async.cg.shared.global [%0], [%1], 16;" :: "r"(dst), "l"(src) : "memory");
}
#define CP_COMMIT() asm volatile("cp.async.commit_group;" ::: "memory")
#define CP_WAIT(n)  asm volatile("cp.async.wait_group %0;" :: "n"(n) : "memory")

__device__ __forceinline__ void ldsm_x4(uint32_t f[4], uint32_t addr) {
    asm volatile("ldmatrix.sync.aligned.m8n8.x4.shared.b16 {%0,%1,%2,%3}, [%4];"
                 : "=r"(f[0]), "=r"(f[1]), "=r"(f[2]), "=r"(f[3]) : "r"(addr));
}
__device__ __forceinline__ void mma16816(float c[4], const uint32_t a[4],
                                         uint32_t b0, uint32_t b1) {
    asm volatile(
        "mma.sync.aligned.m16n8k16.row.col.f32.f16.f16.f32 "
        "{%0,%1,%2,%3}, {%4,%5,%6,%7}, {%8,%9}, {%0,%1,%2,%3};"
        : "+f"(c[0]), "+f"(c[1]), "+f"(c[2]), "+f"(c[3])
        : "r"(a[0]), "r"(a[1]), "r"(a[2]), "r"(a[3]), "r"(b0), "r"(b1));
}

// ---------------- kernel 1: A[b, (d-1)*512+i] = T_d(tanh(x[b,i])) fp16 -------
__global__ void gen_a_kernel(const float* __restrict__ x, __half* __restrict__ A) {
    int b = blockIdx.x;
    int t = threadIdx.x;  // 0..255 -> i = 2t, 2t+1
    float2 xv = *reinterpret_cast<const float2*>(x + (size_t)b * IN_F + 2 * t);
    float ua = tanhf(xv.x);
    float ub = tanhf(xv.y);
    __half2* dst = reinterpret_cast<__half2*>(A + (size_t)b * KP + 2 * t);
    float pa = 1.0f, pb = 1.0f;   // T_0
    float ca = ua,  cb = ub;      // T_1
    dst[0] = __floats2half2_rn(ua, ub);          // d=1 at offset 0
#pragma unroll
    for (int d = 2; d <= 8; d++) {
        float na = 2.0f * ua * ca - pa;
        float nb = 2.0f * ub * cb - pb;
        dst[(d - 1) * (IN_F / 2)] = __floats2half2_rn(na, nb);
        pa = ca; pb = cb; ca = na; cb = nb;
    }
}

// ---------------- kernel 2: B[o, (d-1)*512+i] = 4096*C[i,o,d]; bias ----------
__global__ void gen_b_kernel(const float* __restrict__ c, __half* __restrict__ B,
                             float* __restrict__ bias) {
    __shared__ float red[IN_F];
    int o = blockIdx.x;
    int i = threadIdx.x;                  // 0..511
    const float* src = c + ((size_t)i * OUT_F + o) * 9;
    red[i] = src[0];
    __half* dst = B + (size_t)o * KP + i;
#pragma unroll
    for (int d = 1; d <= 8; d++)
        dst[(d - 1) * IN_F] = __float2half_rn(src[d] * COEF_SCALE);
    __syncthreads();
#pragma unroll
    for (int s = IN_F / 2; s > 0; s >>= 1) {
        if (i < s) red[i] += red[i + s];
        __syncthreads();
    }
    if (i == 0) bias[o] = red[0] * COEF_SCALE;
}

// ---------------- kernel 3: mma.sync GEMM  M=32768 N=512 K'=4096 -------------
// 512 threads, 16 warps in 4(m) x 4(n) grid: warp tile 32 x 64.
// 4-stage cp.async pipeline, XOR-swizzled smem, bias-initialized accumulators.
__global__ __launch_bounds__(512, 1)
void gemm_kernel(const __half* __restrict__ A, const __half* __restrict__ Bw,
                 const float* __restrict__ bias, float* __restrict__ out) {
    extern __shared__ __align__(1024) char smem[];
    uint32_t sb = smem_u32(smem);
    int tid = threadIdx.x;
    int wid = tid >> 5, lid = tid & 31;
    int m0 = blockIdx.y * BM;
    int n0 = blockIdx.x * BN;
    int wm = wid & 3;          // m stripe of 32
    int wn = wid >> 2;         // n stripe of 64

    // acc init = bias (T_0 contribution, pre-scaled by 4096)
    float acc[2][8][4];
    {
        int ncol = (lid & 3) * 2;
#pragma unroll
        for (int ni = 0; ni < 8; ni++) {
            int n = n0 + wn * 64 + ni * 8 + ncol;
            float b0 = __ldg(bias + n);
            float b1 = __ldg(bias + n + 1);
#pragma unroll
            for (int mi = 0; mi < 2; mi++) {
                acc[mi][ni][0] = b0; acc[mi][ni][1] = b1;
                acc[mi][ni][2] = b0; acc[mi][ni][3] = b1;
            }
        }
    }

    int g_row = tid >> 3;          // 0..63
    int g_c   = tid & 7;           // 0..7

#define ISSUE_STAGE(it_)                                                          \
    do {                                                                          \
        int s_ = (it_) % NSTAGE;                                                  \
        uint32_t ab_ = sb + s_ * STAGE_BYTES;                                     \
        uint32_t bb_ = ab_ + ASTAGE_BYTES;                                        \
        int k0_ = (it_) * BK;                                                     \
        const char* agm_ = (const char*)(A + (size_t)m0 * KP + k0_);              \
        _Pragma("unroll")                                                         \
        for (int r_ = 0; r_ < 2; r_++) {                                          \
            int row_ = g_row + r_ * 64;                                           \
            uint32_t dst_ = ab_ + row_ * 128 + ((g_c ^ (row_ & 7)) << 4);         \
            cp_async16(dst_, agm_ + (size_t)row_ * (KP * 2) + g_c * 16);          \
        }                                                                         \
        const char* bgm_ = (const char*)(Bw + (size_t)n0 * KP + k0_);             \
        _Pragma("unroll")                                                         \
        for (int r_ = 0; r_ < 4; r_++) {                                          \
            int row_ = g_row + r_ * 64;                                           \
            uint32_t dst_ = bb_ + row_ * 128 + ((g_c ^ (row_ & 7)) << 4);         \
            cp_async16(dst_, bgm_ + (size_t)row_ * (KP * 2) + g_c * 16);          \
        }                                                                         \
    } while (0)

    ISSUE_STAGE(0); CP_COMMIT();
    ISSUE_STAGE(1); CP_COMMIT();
    ISSUE_STAGE(2); CP_COMMIT();

    int lr = lid & 7;
    int lt = lid >> 3;

    for (int it = 0; it < NITER; it++) {
        CP_WAIT(2);
        __syncthreads();
        if (it + 3 < NITER) { ISSUE_STAGE(it + 3); }
        CP_COMMIT();

        uint32_t abase = sb + (it % NSTAGE) * STAGE_BYTES;
        uint32_t bbase = abase + ASTAGE_BYTES;

#pragma unroll
        for (int ks = 0; ks < 4; ks++) {
            uint32_t afr[2][4];
#pragma unroll
            for (int mi = 0; mi < 2; mi++) {
                int m = wm * 32 + mi * 16 + (lt & 1) * 8 + lr;
                int g = ks * 2 + (lt >> 1);
                ldsm_x4(afr[mi], abase + m * 128 + ((g ^ (m & 7)) << 4));
            }
#pragma unroll
            for (int nb = 0; nb < 4; nb++) {
                uint32_t bfr[4];
                int n = wn * 64 + nb * 16 + (lt & 1) * 8 + lr;
                int g = ks * 2 + (lt >> 1);
                ldsm_x4(bfr, bbase + n * 128 + ((g ^ (n & 7)) << 4));
#pragma unroll
                for (int h = 0; h < 2; h++)
#pragma unroll
                    for (int mi = 0; mi < 2; mi++)
                        mma16816(acc[mi][2 * nb + h], afr[mi], bfr[h], bfr[h + 2]);
            }
        }
        __syncthreads();
    }

    // ---------------- epilogue ----------------
    int mrow = lid >> 2;
    int ncol = (lid & 3) * 2;
#pragma unroll
    for (int mi = 0; mi < 2; mi++) {
#pragma unroll
        for (int ni = 0; ni < 8; ni++) {
            int n = n0 + wn * 64 + ni * 8 + ncol;
            int m_lo = m0 + wm * 32 + mi * 16 + mrow;
            float2 v0, v1;
            v0.x = acc[mi][ni][0] * OUT_SCALE;
            v0.y = acc[mi][ni][1] * OUT_SCALE;
            v1.x = acc[mi][ni][2] * OUT_SCALE;
            v1.y = acc[mi][ni][3] * OUT_SCALE;
            *reinterpret_cast<float2*>(out + (size_t)m_lo * OUT_F + n) = v0;
            *reinterpret_cast<float2*>(out + (size_t)(m_lo + 8) * OUT_F + n) = v1;
        }
    }
#undef ISSUE_STAGE
}

// ---------------- launch ------------------------------------------------------
extern "C" void kernel_launch(void* const* d_in, const int* in_sizes, int n_in,
                              void* d_out, int out_size) {
    const float* x     = (const float*)d_in[0];
    const float* coeff = (const float*)d_in[1];
    float* out = (float*)d_out;

    void* pA = nullptr;
    void* pB = nullptr;
    void* pBias = nullptr;
    cudaGetSymbolAddress(&pA, g_A);
    cudaGetSymbolAddress(&pB, g_B);
    cudaGetSymbolAddress(&pBias, g_bias);

    gen_a_kernel<<<BATCH, 256>>>(x, (__half*)pA);
    gen_b_kernel<<<OUT_F, IN_F>>>(coeff, (__half*)pB, (float*)pBias);

    cudaFuncSetAttribute(gemm_kernel, cudaFuncAttributeMaxDynamicSharedMemorySize,
                         SMEM_TOTAL);
    dim3 grid(OUT_F / BN, BATCH / BM);   // (2, 256)
    gemm_kernel<<<grid, 512, SMEM_TOTAL>>>((const __half*)pA, (const __half*)pB,
                                           (const float*)pBias, out);
}